// round 2
// baseline (speedup 1.0000x reference)
#include <cuda_runtime.h>
#include <math.h>

#define BB   128
#define SS   400
#define HH   256
#define EE   128
#define VV   50000
#define PADV 250
#define VP   (VV + PADV)

// ---------------- static scratch (no allocations allowed) ----------------
__device__ float    g_gi[BB * 768];
__device__ float    g_gh[BB * 768];
__device__ float    g_decctx[BB * 512];   // [h_new | context]
__device__ float    g_wsh[BB * HH];       // w_s*h_new + att_bias
__device__ float    g_scores[BB * SS];
__device__ float    g_hid[BB * EE];
__device__ float    g_logits[BB * VV];
__device__ unsigned g_rowmax[BB];
__device__ float    g_rowsum[BB];
__device__ float    g_pgen[BB];

// ---------------- helpers ----------------
__device__ __forceinline__ float sigm(float x)   { return 1.f / (1.f + __expf(-x)); }
// exact identity tanh(x) = 1 - 2/(e^{2x}+1); __expf rel err ~1e-6 -> safe for 1e-3 tol
__device__ __forceinline__ float tanh_e(float x) { return 1.f - 2.f / (__expf(2.f * x) + 1.f); }

// monotone float <-> uint mapping for atomicMax on floats
__device__ __forceinline__ unsigned fmap(float f) {
    int b = __float_as_int(f);
    return (b >= 0) ? ((unsigned)b | 0x80000000u) : (unsigned)(~b);
}
__device__ __forceinline__ float funmap(unsigned u) {
    int b = (u & 0x80000000u) ? (int)(u & 0x7fffffffu) : ~(int)u;
    return __int_as_float(b);
}

// packed fp32x2 FMA (Blackwell): d = a*b + d elementwise on two packed fp32
__device__ __forceinline__ void fma2(unsigned long long& d, unsigned long long a, unsigned long long b) {
    asm("fma.rn.f32x2 %0, %1, %2, %3;" : "=l"(d) : "l"(a), "l"(b), "l"(d));
}
__device__ __forceinline__ float unpack_sum(unsigned long long v) {
    float lo, hi;
    asm("mov.b64 {%0,%1}, %2;" : "=f"(lo), "=f"(hi) : "l"(v));
    return lo + hi;
}

// ---------------- init scratch ----------------
__global__ void init_kernel() {
    int i = blockIdx.x * 256 + threadIdx.x;   // grid 384 -> covers 98304
    if (i < BB * 768) { g_gi[i] = 0.f; g_gh[i] = 0.f; }
    if (i < BB * EE)  g_hid[i] = 0.f;
    if (i < BB)       { g_rowmax[i] = 0u; g_rowsum[i] = 0.f; }
}

// ---------------- f32x2 tiled GEMM ----------------
// C[m][n] = sum_k A[m][k] * W[n][k] (+ bias[n]); M fixed 128, BN = 64, BK = 16.
// 256 threads (16 ty x 16 tx), microtile 8m x 4n, float2-packed along k.
// SPLIT: grid.z k-chunks, atomicAdd into pre-zeroed C, bias added by z==0.
// DOMAX: (non-split) fused per-row max -> g_rowmax via shared+global atomicMax.
// GATHER: A row index taken from gidx[m] (embedding lookup).
template <bool SPLIT, bool DOMAX, bool GATHER>
__global__ __launch_bounds__(256) void gemm64(
    const float* __restrict__ A, const float* __restrict__ W,
    const float* __restrict__ bias, float* __restrict__ C,
    const int* __restrict__ gidx, int N, int K, int kChunk,
    unsigned* __restrict__ rowMax)
{
    __shared__ float2 As[8][132];
    __shared__ float2 Ws[8][68];
    __shared__ unsigned smax[128];

    const int tid = threadIdx.x;
    const int tx = tid & 15;
    const int ty = tid >> 4;
    const int n0 = blockIdx.x * 64;
    const int k0   = SPLIT ? blockIdx.z * kChunk : 0;
    const int kEnd = SPLIT ? k0 + kChunk : K;

    if (DOMAX && tid < 128) smax[tid] = 0u;

    unsigned long long acc[8][4];
#pragma unroll
    for (int i = 0; i < 8; i++)
#pragma unroll
        for (int j = 0; j < 4; j++) acc[i][j] = 0ULL;

    for (int kt = k0; kt < kEnd; kt += 16) {
        __syncthreads();
        // A tile: 128 m x 8 kp float2 = 1024 elems, 4 per thread
#pragma unroll
        for (int t = 0; t < 4; t++) {
            int lin = tid + t * 256;
            int m  = lin >> 3;
            int kp = lin & 7;
            int row = GATHER ? gidx[m] : m;
            As[kp][m] = *reinterpret_cast<const float2*>(A + (size_t)row * K + kt + 2 * kp);
        }
        // W tile: 64 n x 8 kp float2 = 512 elems, 2 per thread
#pragma unroll
        for (int t = 0; t < 2; t++) {
            int lin = tid + t * 256;
            int nn = lin >> 3;
            int kp = lin & 7;
            int row = n0 + nn;
            if (row >= N) row = N - 1;   // clamp (store is guarded)
            Ws[kp][nn] = *reinterpret_cast<const float2*>(W + (size_t)row * K + kt + 2 * kp);
        }
        __syncthreads();

#pragma unroll
        for (int kp = 0; kp < 8; kp++) {
            unsigned long long a[8], w[4];
            const ulonglong2* ap = reinterpret_cast<const ulonglong2*>(&As[kp][ty * 8]);
            ulonglong2 q0 = ap[0], q1 = ap[1], q2 = ap[2], q3 = ap[3];
            a[0] = q0.x; a[1] = q0.y; a[2] = q1.x; a[3] = q1.y;
            a[4] = q2.x; a[5] = q2.y; a[6] = q3.x; a[7] = q3.y;
            const ulonglong2* wp = reinterpret_cast<const ulonglong2*>(&Ws[kp][tx * 4]);
            ulonglong2 r0 = wp[0], r1 = wp[1];
            w[0] = r0.x; w[1] = r0.y; w[2] = r1.x; w[3] = r1.y;
#pragma unroll
            for (int i = 0; i < 8; i++)
#pragma unroll
                for (int j = 0; j < 4; j++) fma2(acc[i][j], a[i], w[j]);
        }
    }

    // epilogue
#pragma unroll
    for (int i = 0; i < 8; i++) {
        int m = ty * 8 + i;
        float mloc = -INFINITY;
#pragma unroll
        for (int j = 0; j < 4; j++) {
            int n = n0 + tx * 4 + j;
            if (n < N) {
                float c = unpack_sum(acc[i][j]);
                if (SPLIT) {
                    if (blockIdx.z == 0 && bias) c += bias[n];
                    atomicAdd(&C[(size_t)m * N + n], c);
                } else {
                    if (bias) c += bias[n];
                    C[(size_t)m * N + n] = c;
                    if (DOMAX) mloc = fmaxf(mloc, c);
                }
            }
        }
        if (DOMAX) atomicMax(&smax[m], fmap(mloc));
    }
    if (DOMAX) {
        __syncthreads();
        if (tid < 128) atomicMax(&rowMax[tid], smax[tid]);
    }
}

// ---------------- GRU gates ----------------
__global__ void gru_kernel(const float* __restrict__ hprev,
                           const float* __restrict__ b_ih, const float* __restrict__ b_hh,
                           const float* __restrict__ w_s,  const float* __restrict__ attb,
                           float* __restrict__ out_h)
{
    int i = blockIdx.x * 256 + threadIdx.x;   // 32768
    int b = i >> 8, h = i & 255;
    const float* gi = g_gi + b * 768;
    const float* gh = g_gh + b * 768;
    float ir = gi[h]       + b_ih[h];
    float iz = gi[256 + h] + b_ih[256 + h];
    float in_ = gi[512 + h] + b_ih[512 + h];
    float hr = gh[h]       + b_hh[h];
    float hz = gh[256 + h] + b_hh[256 + h];
    float hn = gh[512 + h] + b_hh[512 + h];
    float r = sigm(ir + hr);
    float z = sigm(iz + hz);
    float n = tanh_e(in_ + r * hn);
    float hnew = (1.f - z) * n + z * hprev[i];
    out_h[i] = hnew;
    g_decctx[b * 512 + h] = hnew;
    g_wsh[i] = fmaf(w_s[h], hnew, attb[0]);
}

// ---------------- attention scores ----------------
__global__ void scores_kernel(const float* __restrict__ enc,
                              const float* __restrict__ w_h,
                              const float* __restrict__ attv)
{
    int b = blockIdx.y;
    int wid = threadIdx.x >> 5, lane = threadIdx.x & 31;
    int s = blockIdx.x * 8 + wid;
    if (s >= SS) return;
    const float* e   = enc + ((size_t)b * SS + s) * HH;
    const float* wsh = g_wsh + b * HH;
    float sum = 0.f;
#pragma unroll
    for (int q = 0; q < 8; q++) {
        int h = q * 32 + lane;
        sum += attv[h] * tanh_e(fmaf(w_h[h], e[h], wsh[h]));
    }
#pragma unroll
    for (int o = 16; o; o >>= 1) sum += __shfl_xor_sync(0xffffffffu, sum, o);
    if (lane == 0) g_scores[b * SS + s] = sum;
}

// ---------------- softmax over S=400 ----------------
__global__ void attsoft_kernel(float* __restrict__ out_att)
{
    int b = blockIdx.x, t = threadIdx.x;   // 128 threads
    __shared__ float sc[SS];
    __shared__ float red[128];
    for (int i = t; i < SS; i += 128) sc[i] = g_scores[b * SS + i];
    __syncthreads();
    float m = -1e30f;
    for (int i = t; i < SS; i += 128) m = fmaxf(m, sc[i]);
    red[t] = m; __syncthreads();
    for (int o = 64; o; o >>= 1) { if (t < o) red[t] = fmaxf(red[t], red[t + o]); __syncthreads(); }
    m = red[0]; __syncthreads();
    float s = 0.f;
    for (int i = t; i < SS; i += 128) s += __expf(sc[i] - m);
    red[t] = s; __syncthreads();
    for (int o = 64; o; o >>= 1) { if (t < o) red[t] += red[t + o]; __syncthreads(); }
    float inv = 1.f / red[0];
    for (int i = t; i < SS; i += 128) out_att[b * SS + i] = __expf(sc[i] - m) * inv;
}

// ---------------- context ----------------
__global__ void context_kernel(const float* __restrict__ enc, const float* __restrict__ att)
{
    int b = blockIdx.x, t = threadIdx.x;   // 256 threads = H
    __shared__ float a[SS];
    for (int i = t; i < SS; i += 256) a[i] = att[b * SS + i];
    __syncthreads();
    const float* e = enc + (size_t)b * SS * HH + t;
    float c = 0.f;
#pragma unroll 8
    for (int s = 0; s < SS; s++) c = fmaf(a[s], e[(size_t)s * HH], c);
    g_decctx[b * 512 + 256 + t] = c;
}

// ---------------- p_gen ----------------
__global__ void pgen_kernel(const float* __restrict__ emb, const int* __restrict__ tok,
                            const float* __restrict__ genw, const float* __restrict__ genb,
                            float* __restrict__ out_pg)
{
    int b = blockIdx.x, t = threadIdx.x;   // 64 threads
    float s = 0.f;
    const float* dc = g_decctx + b * 512;
    for (int j = t; j < 512; j += 64) s += dc[j] * genw[j];
    const float* x = emb + (size_t)tok[b] * EE;
    for (int j = t; j < EE; j += 64) s += x[j] * genw[512 + j];
    __shared__ float red[64];
    red[t] = s; __syncthreads();
    for (int o = 32; o; o >>= 1) { if (t < o) red[t] += red[t + o]; __syncthreads(); }
    if (t == 0) {
        float p = sigm(red[0] + genb[0]);
        out_pg[b] = p;
        g_pgen[b] = p;
    }
}

// ---------------- vocab softmax: sum of exp ----------------
__global__ void sumexp_kernel()
{
    int b = blockIdx.y, t = threadIdx.x;   // grid (25, B), 256 thr, 2000 elems/block
    int start = blockIdx.x * 2000;
    float mx = funmap(g_rowmax[b]);
    const float* lg = g_logits + (size_t)b * VV + start;
    float s = 0.f;
    for (int i = t; i < 2000; i += 256) s += __expf(lg[i] - mx);
    __shared__ float red[256];
    red[t] = s; __syncthreads();
    for (int o = 128; o; o >>= 1) { if (t < o) red[t] += red[t + o]; __syncthreads(); }
    if (t == 0) atomicAdd(&g_rowsum[b], red[0]);
}

// ---------------- finalize: p_vocab, p_final base, pad zeros ----------------
__global__ void finalize_kernel(float* __restrict__ out_pv, float* __restrict__ out_pf)
{
    int b = blockIdx.y, t = threadIdx.x;
    int start = blockIdx.x * 2000;
    float mx  = funmap(g_rowmax[b]);
    float inv = 1.f / g_rowsum[b];
    float pg  = g_pgen[b];
    const float* lg = g_logits + (size_t)b * VV + start;
    float* pv = out_pv + (size_t)b * VV + start;
    float* pf = out_pf + (size_t)b * VP + start;
    for (int i = t; i < 2000; i += 256) {
        float e = __expf(lg[i] - mx) * inv;
        pv[i] = e;
        pf[i] = e * pg;
    }
    if (blockIdx.x == 0 && t < PADV) out_pf[(size_t)b * VP + VV + t] = 0.f;
}

// ---------------- copy-mechanism scatter ----------------
__global__ void scatter_kernel(const int* __restrict__ fiv, const float* __restrict__ att,
                               float* __restrict__ out_pf)
{
    int b = blockIdx.x, s = threadIdx.x;   // 512 thr, guard
    if (s < SS) {
        float w = (1.f - g_pgen[b]) * att[b * SS + s];
        atomicAdd(&out_pf[(size_t)b * VP + fiv[b * SS + s]], w);
    }
}

// ---------------- launch ----------------
extern "C" void kernel_launch(void* const* d_in, const int* in_sizes, int n_in,
                              void* d_out, int out_size)
{
    const int*   tok   = (const int*)d_in[0];
    const float* hprev = (const float*)d_in[1];
    const float* enc   = (const float*)d_in[2];
    const int*   fiv   = (const int*)d_in[3];
    const float* emb   = (const float*)d_in[4];
    const float* w_ih  = (const float*)d_in[5];
    const float* w_hh  = (const float*)d_in[6];
    const float* b_ih  = (const float*)d_in[7];
    const float* b_hh  = (const float*)d_in[8];
    const float* w_h   = (const float*)d_in[9];
    const float* w_s   = (const float*)d_in[10];
    const float* attb  = (const float*)d_in[11];
    const float* attv  = (const float*)d_in[12];
    const float* genw  = (const float*)d_in[13];
    const float* genb  = (const float*)d_in[14];
    const float* outhw = (const float*)d_in[15];
    const float* outhb = (const float*)d_in[16];
    const float* outvw = (const float*)d_in[17];
    const float* outvb = (const float*)d_in[18];

    float* out    = (float*)d_out;
    float* out_h  = out;                         // (B,H)            32768
    float* out_pf = out + 32768;                 // (B,VP)           6,432,000
    float* out_pg = out + 6464768;               // (B,1)            128
    float* out_pv = out + 6464896;               // (B,V)            6,400,000
    float* out_at = out + 12864896;              // (B,S)            51,200

    float *p_gi, *p_gh, *p_hid, *p_logits, *p_dc;
    unsigned* p_rm;
    cudaGetSymbolAddress((void**)&p_gi,     g_gi);
    cudaGetSymbolAddress((void**)&p_gh,     g_gh);
    cudaGetSymbolAddress((void**)&p_hid,    g_hid);
    cudaGetSymbolAddress((void**)&p_logits, g_logits);
    cudaGetSymbolAddress((void**)&p_dc,     g_decctx);
    cudaGetSymbolAddress((void**)&p_rm,     g_rowmax);

    init_kernel<<<384, 256>>>();

    // gi = emb[tok] @ w_ih^T     (N=768, K=128, split-K 4)
    gemm64<true, false, true ><<<dim3(12, 1, 4), 256>>>(emb,   w_ih,  nullptr, p_gi,  tok,     768, EE, 32, nullptr);
    // gh = hprev @ w_hh^T        (N=768, K=256, split-K 8)
    gemm64<true, false, false><<<dim3(12, 1, 8), 256>>>(hprev, w_hh,  nullptr, p_gh,  nullptr, 768, HH, 32, nullptr);

    gru_kernel<<<128, 256>>>(hprev, b_ih, b_hh, w_s, attb, out_h);

    scores_kernel<<<dim3(50, 128), 256>>>(enc, w_h, attv);
    attsoft_kernel<<<128, 128>>>(out_at);
    context_kernel<<<128, 256>>>(enc, out_at);
    pgen_kernel<<<128, 64>>>(emb, tok, genw, genb, out_pg);

    // hid = dec_ctx @ outh_w^T   (N=128, K=512, split-K 16, +outh_b)
    gemm64<true, false, false><<<dim3(2, 1, 16), 256>>>(p_dc, outhw, outhb, p_hid, nullptr, EE, 512, 32, nullptr);
    // logits = hid @ outv_w^T + outv_b   (N=50000, K=128) + fused row-max
    gemm64<false, true, false><<<dim3(782, 1, 1), 256>>>(p_hid, outvw, outvb, p_logits, nullptr, VV, EE, 0, p_rm);

    sumexp_kernel<<<dim3(25, 128), 256>>>();
    finalize_kernel<<<dim3(25, 128), 256>>>(out_pv, out_pf);
    scatter_kernel<<<128, 512>>>(fiv, out_at, out_pf);
}

// round 7
// speedup vs baseline: 1.3109x; 1.3109x over previous
#include <cuda_runtime.h>
#include <cuda_bf16.h>
#include <math.h>

#define BB   128
#define SS   400
#define HH   256
#define EE   128
#define VV   50000
#define PADV 250
#define VP   (VV + PADV)
#define NTILES_L 782          // ceil(50000/64)
#define TSTRIDE  784

// ---------------- static scratch ----------------
__device__ float g_gi[BB * 768];
__device__ float g_gh[BB * 768];
__device__ float g_decctx[BB * 512];   // [h_new | context]
__device__ float g_wsh[BB * HH];
__device__ float g_scores[BB * SS];
__device__ float g_hid[BB * EE];
__device__ float g_logits[(size_t)BB * VV];
__device__ float g_tmax[BB * TSTRIDE];
__device__ float g_tsum[BB * TSTRIDE];
__device__ float g_rowmax[BB];
__device__ float g_rowsum[BB];
__device__ float g_pgen[BB];

// ---------------- math helpers (MUFU only, no div.rn) ----------------
__device__ __forceinline__ float sigm(float x)   { return __fdividef(1.f, 1.f + __expf(-x)); }
__device__ __forceinline__ float tanh_e(float x) { return 1.f - __fdividef(2.f, __expf(2.f * x) + 1.f); }

// packed fp32x2 FMA (Blackwell-only PTX; exact fp32 semantics)
__device__ __forceinline__ void fma2(unsigned long long& d, unsigned long long a, unsigned long long b) {
    asm("fma.rn.f32x2 %0, %1, %2, %3;" : "=l"(d) : "l"(a), "l"(b), "l"(d));
}
__device__ __forceinline__ float unpack_sum(unsigned long long v) {
    float lo, hi;
    asm("mov.b64 {%0,%1}, %2;" : "=f"(lo), "=f"(hi) : "l"(v));
    return lo + hi;
}

// ---------------- init scratch ----------------
__global__ void init_kernel() {
    int i = blockIdx.x * 256 + threadIdx.x;   // grid 384 -> 98304
    if (i < BB * 768) { g_gi[i] = 0.f; g_gh[i] = 0.f; }
    if (i < BB * EE)  g_hid[i] = 0.f;
}

// ---------------- f32x2 tiled split-K GEMM (small GEMMs) ----------------
template <bool GATHER>
__global__ __launch_bounds__(256) void gemm64(
    const float* __restrict__ A, const float* __restrict__ W,
    const float* __restrict__ bias, float* __restrict__ C,
    const int* __restrict__ gidx, int N, int K, int kChunk)
{
    __shared__ float2 As[8][132];
    __shared__ float2 Ws[8][68];

    const int tid = threadIdx.x;
    const int tx = tid & 15;
    const int ty = tid >> 4;
    const int n0 = blockIdx.x * 64;
    const int k0 = blockIdx.z * kChunk;
    const int kEnd = k0 + kChunk;

    unsigned long long acc[8][4];
#pragma unroll
    for (int i = 0; i < 8; i++)
#pragma unroll
        for (int j = 0; j < 4; j++) acc[i][j] = 0ULL;

    for (int kt = k0; kt < kEnd; kt += 16) {
        __syncthreads();
#pragma unroll
        for (int t = 0; t < 4; t++) {
            int lin = tid + t * 256;
            int m = lin >> 3, kp = lin & 7;
            int row = GATHER ? gidx[m] : m;
            As[kp][m] = *reinterpret_cast<const float2*>(A + (size_t)row * K + kt + 2 * kp);
        }
#pragma unroll
        for (int t = 0; t < 2; t++) {
            int lin = tid + t * 256;
            int nn = lin >> 3, kp = lin & 7;
            int row = n0 + nn;
            if (row >= N) row = N - 1;
            Ws[kp][nn] = *reinterpret_cast<const float2*>(W + (size_t)row * K + kt + 2 * kp);
        }
        __syncthreads();

#pragma unroll
        for (int kp = 0; kp < 8; kp++) {
            unsigned long long a[8], w[4];
            const ulonglong2* ap = reinterpret_cast<const ulonglong2*>(&As[kp][ty * 8]);
            ulonglong2 q0 = ap[0], q1 = ap[1], q2 = ap[2], q3 = ap[3];
            a[0] = q0.x; a[1] = q0.y; a[2] = q1.x; a[3] = q1.y;
            a[4] = q2.x; a[5] = q2.y; a[6] = q3.x; a[7] = q3.y;
            const ulonglong2* wp = reinterpret_cast<const ulonglong2*>(&Ws[kp][tx * 4]);
            ulonglong2 r0 = wp[0], r1 = wp[1];
            w[0] = r0.x; w[1] = r0.y; w[2] = r1.x; w[3] = r1.y;
#pragma unroll
            for (int i = 0; i < 8; i++)
#pragma unroll
                for (int j = 0; j < 4; j++) fma2(acc[i][j], a[i], w[j]);
        }
    }

#pragma unroll
    for (int i = 0; i < 8; i++) {
        int m = ty * 8 + i;
#pragma unroll
        for (int j = 0; j < 4; j++) {
            int n = n0 + tx * 4 + j;
            if (n < N) {
                float c = unpack_sum(acc[i][j]);
                if (blockIdx.z == 0 && bias) c += bias[n];
                atomicAdd(&C[(size_t)m * N + n], c);
            }
        }
    }
}

// ---------------- GRU gates ----------------
__global__ void gru_kernel(const float* __restrict__ hprev,
                           const float* __restrict__ b_ih, const float* __restrict__ b_hh,
                           const float* __restrict__ w_s, const float* __restrict__ attb,
                           float* __restrict__ out_h)
{
    int i = blockIdx.x * 256 + threadIdx.x;
    int b = i >> 8, h = i & 255;
    const float* gi = g_gi + b * 768;
    const float* gh = g_gh + b * 768;
    float ir = gi[h] + b_ih[h];
    float iz = gi[256 + h] + b_ih[256 + h];
    float in_ = gi[512 + h] + b_ih[512 + h];
    float hr = gh[h] + b_hh[h];
    float hz = gh[256 + h] + b_hh[256 + h];
    float hn = gh[512 + h] + b_hh[512 + h];
    float r = sigm(ir + hr);
    float z = sigm(iz + hz);
    float n = tanh_e(in_ + r * hn);
    float hnew = (1.f - z) * n + z * hprev[i];
    out_h[i] = hnew;
    g_decctx[b * 512 + h] = hnew;
    g_wsh[i] = fmaf(w_s[h], hnew, attb[0]);
}

// ---------------- attention scores ----------------
__global__ void scores_kernel(const float* __restrict__ enc,
                              const float* __restrict__ w_h,
                              const float* __restrict__ attv)
{
    int b = blockIdx.y;
    int wid = threadIdx.x >> 5, lane = threadIdx.x & 31;
    int s = blockIdx.x * 8 + wid;
    if (s >= SS) return;
    const float* e = enc + ((size_t)b * SS + s) * HH;
    const float* wsh = g_wsh + b * HH;
    float sum = 0.f;
#pragma unroll
    for (int q = 0; q < 8; q++) {
        int h = q * 32 + lane;
        sum += attv[h] * tanh_e(fmaf(w_h[h], e[h], wsh[h]));
    }
#pragma unroll
    for (int o = 16; o; o >>= 1) sum += __shfl_xor_sync(0xffffffffu, sum, o);
    if (lane == 0) g_scores[b * SS + s] = sum;
}

// ---------------- fused: att softmax + context + p_gen (one block per b) ----------------
__global__ __launch_bounds__(1024) void attn_tail_kernel(
    const float* __restrict__ enc, const float* __restrict__ emb,
    const int* __restrict__ tok, const float* __restrict__ genw,
    const float* __restrict__ genb,
    float* __restrict__ out_at, float* __restrict__ out_pg)
{
    int b = blockIdx.x, t = threadIdx.x;
    __shared__ float att[SS];
    __shared__ float red[1024];
    __shared__ float ctx[HH];

    // softmax over S=400
    float v = (t < SS) ? g_scores[b * SS + t] : -INFINITY;
    if (t < SS) att[t] = v;
    red[t] = v; __syncthreads();
    for (int o = 512; o; o >>= 1) { if (t < o) red[t] = fmaxf(red[t], red[t + o]); __syncthreads(); }
    float mx = red[0]; __syncthreads();
    float ev = (t < SS) ? __expf(v - mx) : 0.f;
    red[t] = ev; __syncthreads();
    for (int o = 512; o; o >>= 1) { if (t < o) red[t] += red[t + o]; __syncthreads(); }
    float inv = __fdividef(1.f, red[0]); __syncthreads();
    if (t < SS) {
        float a = ev * inv;
        att[t] = a;
        out_at[b * SS + t] = a;
    }
    __syncthreads();

    // context: 4-way split over S per h
    {
        int h = t & 255;
        int part = t >> 8;          // 0..3
        int sBeg = part * 100;
        const float* e = enc + (size_t)b * SS * HH + (size_t)sBeg * HH + h;
        float c = 0.f;
#pragma unroll 10
        for (int s = 0; s < 100; s++) c = fmaf(att[sBeg + s], e[(size_t)s * HH], c);
        red[t] = c;
    }
    __syncthreads();
    if (t < 512) red[t] += red[t + 512];
    __syncthreads();
    if (t < 256) {
        float c = red[t] + red[t + 256];
        ctx[t] = c;
        g_decctx[b * 512 + 256 + t] = c;
    }
    __syncthreads();

    // p_gen: dot(genw, [h_new | ctx | x])
    float pv = 0.f;
    if (t < 256)       pv = g_decctx[b * 512 + t] * genw[t];
    else if (t < 512)  pv = ctx[t - 256] * genw[t];
    else if (t < 640)  pv = emb[(size_t)tok[b] * EE + (t - 512)] * genw[t];
    red[t] = pv; __syncthreads();
    for (int o = 512; o; o >>= 1) { if (t < o) red[t] += red[t + o]; __syncthreads(); }
    if (t == 0) {
        float p = sigm(red[0] + genb[0]);
        out_pg[b] = p;
        g_pgen[b] = p;
    }
}

// ---------------- logits GEMM (FFMA2) + fused bias / tile-max / tile-sumexp ----------------
__global__ __launch_bounds__(256, 2) void logits_kernel(
    const float* __restrict__ A, const float* __restrict__ W,
    const float* __restrict__ bias, float* __restrict__ C)
{
    __shared__ float2 As[8][132];
    __shared__ float2 Ws[8][68];

    const int tid = threadIdx.x;
    const int tx = tid & 15;
    const int ty = tid >> 4;
    const int n0 = blockIdx.x * 64;

    unsigned long long acc[8][4];
#pragma unroll
    for (int i = 0; i < 8; i++)
#pragma unroll
        for (int j = 0; j < 4; j++) acc[i][j] = 0ULL;

    for (int kt = 0; kt < EE; kt += 16) {
        __syncthreads();
#pragma unroll
        for (int t = 0; t < 4; t++) {
            int lin = tid + t * 256;
            int m = lin >> 3, kp = lin & 7;
            As[kp][m] = *reinterpret_cast<const float2*>(A + (size_t)m * EE + kt + 2 * kp);
        }
#pragma unroll
        for (int t = 0; t < 2; t++) {
            int lin = tid + t * 256;
            int nn = lin >> 3, kp = lin & 7;
            int row = n0 + nn;
            if (row >= VV) row = VV - 1;
            Ws[kp][nn] = *reinterpret_cast<const float2*>(W + (size_t)row * EE + kt + 2 * kp);
        }
        __syncthreads();

#pragma unroll
        for (int kp = 0; kp < 8; kp++) {
            unsigned long long a[8], w[4];
            const ulonglong2* ap = reinterpret_cast<const ulonglong2*>(&As[kp][ty * 8]);
            ulonglong2 q0 = ap[0], q1 = ap[1], q2 = ap[2], q3 = ap[3];
            a[0] = q0.x; a[1] = q0.y; a[2] = q1.x; a[3] = q1.y;
            a[4] = q2.x; a[5] = q2.y; a[6] = q3.x; a[7] = q3.y;
            const ulonglong2* wp = reinterpret_cast<const ulonglong2*>(&Ws[kp][tx * 4]);
            ulonglong2 r0 = wp[0], r1 = wp[1];
            w[0] = r0.x; w[1] = r0.y; w[2] = r1.x; w[3] = r1.y;
#pragma unroll
            for (int i = 0; i < 8; i++)
#pragma unroll
                for (int j = 0; j < 4; j++) fma2(acc[i][j], a[i], w[j]);
        }
    }

    // epilogue: bias add, store logits, per-(row,tile) max + sumexp partials
#pragma unroll
    for (int i = 0; i < 8; i++) {
        int m = ty * 8 + i;
        float v[4];
        float mloc = -INFINITY;
#pragma unroll
        for (int j = 0; j < 4; j++) {
            int n = n0 + tx * 4 + j;
            bool valid = n < VV;
            int nc = valid ? n : VV - 1;
            float c = unpack_sum(acc[i][j]) + __ldg(bias + nc);
            if (valid) {
                C[(size_t)m * VV + n] = c;
                mloc = fmaxf(mloc, c);
                v[j] = c;
            } else {
                v[j] = -INFINITY;
            }
        }
        // max over the 16 tx lanes (xor <=8 stays within each 16-lane half)
#pragma unroll
        for (int o = 8; o; o >>= 1) mloc = fmaxf(mloc, __shfl_xor_sync(0xffffffffu, mloc, o));
        float s = 0.f;
#pragma unroll
        for (int j = 0; j < 4; j++) if (v[j] > -INFINITY) s += __expf(v[j] - mloc);
#pragma unroll
        for (int o = 8; o; o >>= 1) s += __shfl_xor_sync(0xffffffffu, s, o);
        if (tx == 0) {
            g_tmax[m * TSTRIDE + blockIdx.x] = mloc;
            g_tsum[m * TSTRIDE + blockIdx.x] = s;
        }
    }
}

// ---------------- merge softmax partials ----------------
__global__ void merge_kernel()
{
    int b = blockIdx.x, t = threadIdx.x;   // 128 threads
    __shared__ float red[128];
    float mx = -INFINITY;
    for (int i = t; i < NTILES_L; i += 128) mx = fmaxf(mx, g_tmax[b * TSTRIDE + i]);
    red[t] = mx; __syncthreads();
    for (int o = 64; o; o >>= 1) { if (t < o) red[t] = fmaxf(red[t], red[t + o]); __syncthreads(); }
    mx = red[0]; __syncthreads();
    float s = 0.f;
    for (int i = t; i < NTILES_L; i += 128)
        s += g_tsum[b * TSTRIDE + i] * __expf(g_tmax[b * TSTRIDE + i] - mx);
    red[t] = s; __syncthreads();
    for (int o = 64; o; o >>= 1) { if (t < o) red[t] += red[t + o]; __syncthreads(); }
    if (t == 0) { g_rowmax[b] = mx; g_rowsum[b] = red[0]; }
}

// ---------------- finalize ----------------
__global__ void finalize_kernel(float* __restrict__ out_pv, float* __restrict__ out_pf)
{
    int b = blockIdx.y, t = threadIdx.x;
    int start = blockIdx.x * 2000;
    float mx = g_rowmax[b];
    float inv = __fdividef(1.f, g_rowsum[b]);
    float pg = g_pgen[b];
    const float* lg = g_logits + (size_t)b * VV + start;
    float* pv = out_pv + (size_t)b * VV + start;
    float* pf = out_pf + (size_t)b * VP + start;
    for (int i = t; i < 2000; i += 256) {
        float e = __expf(lg[i] - mx) * inv;
        pv[i] = e;
        pf[i] = e * pg;
    }
    if (blockIdx.x == 0 && t < PADV) out_pf[(size_t)b * VP + VV + t] = 0.f;
}

// ---------------- copy-mechanism scatter ----------------
__global__ void scatter_kernel(const int* __restrict__ fiv, const float* __restrict__ att,
                               float* __restrict__ out_pf)
{
    int b = blockIdx.x, s = threadIdx.x;
    if (s < SS) {
        float w = (1.f - g_pgen[b]) * att[b * SS + s];
        atomicAdd(&out_pf[(size_t)b * VP + fiv[b * SS + s]], w);
    }
}

// ---------------- launch ----------------
extern "C" void kernel_launch(void* const* d_in, const int* in_sizes, int n_in,
                              void* d_out, int out_size)
{
    const int*   tok   = (const int*)d_in[0];
    const float* hprev = (const float*)d_in[1];
    const float* enc   = (const float*)d_in[2];
    const int*   fiv   = (const int*)d_in[3];
    const float* emb   = (const float*)d_in[4];
    const float* w_ih  = (const float*)d_in[5];
    const float* w_hh  = (const float*)d_in[6];
    const float* b_ih  = (const float*)d_in[7];
    const float* b_hh  = (const float*)d_in[8];
    const float* w_h   = (const float*)d_in[9];
    const float* w_s   = (const float*)d_in[10];
    const float* attb  = (const float*)d_in[11];
    const float* attv  = (const float*)d_in[12];
    const float* genw  = (const float*)d_in[13];
    const float* genb  = (const float*)d_in[14];
    const float* outhw = (const float*)d_in[15];
    const float* outhb = (const float*)d_in[16];
    const float* outvw = (const float*)d_in[17];
    const float* outvb = (const float*)d_in[18];

    float* out    = (float*)d_out;
    float* out_h  = out;
    float* out_pf = out + 32768;
    float* out_pg = out + 6464768;
    float* out_pv = out + 6464896;
    float* out_at = out + 12864896;

    float *p_gi, *p_gh, *p_hid, *p_logits, *p_dc;
    cudaGetSymbolAddress((void**)&p_gi,     g_gi);
    cudaGetSymbolAddress((void**)&p_gh,     g_gh);
    cudaGetSymbolAddress((void**)&p_hid,    g_hid);
    cudaGetSymbolAddress((void**)&p_logits, g_logits);
    cudaGetSymbolAddress((void**)&p_dc,     g_decctx);

    init_kernel<<<384, 256>>>();

    gemm64<true ><<<dim3(12, 1, 4), 256>>>(emb,   w_ih, nullptr, p_gi, tok,     768, EE, 32);
    gemm64<false><<<dim3(12, 1, 8), 256>>>(hprev, w_hh, nullptr, p_gh, nullptr, 768, HH, 32);

    gru_kernel<<<128, 256>>>(hprev, b_ih, b_hh, w_s, attb, out_h);

    scores_kernel<<<dim3(50, 128), 256>>>(enc, w_h, attv);
    attn_tail_kernel<<<128, 1024>>>(enc, emb, tok, genw, genb, out_at, out_pg);

    gemm64<false><<<dim3(2, 1, 16), 256>>>(p_dc, outhw, outhb, p_hid, nullptr, EE, 512, 32);

    logits_kernel<<<NTILES_L, 256>>>(p_hid, outvw, outvb, p_logits);
    merge_kernel<<<128, 128>>>();

    finalize_kernel<<<dim3(25, 128), 256>>>(out_pv, out_pf);
    scatter_kernel<<<128, 512>>>(fiv, out_at, out_pf);
}

// round 8
// speedup vs baseline: 1.4059x; 1.0725x over previous
#include <cuda_runtime.h>
#include <cuda_bf16.h>
#include <math.h>

#define BB   128
#define SS   400
#define HH   256
#define EE   128
#define VV   50000
#define PADV 250
#define VP   (VV + PADV)
#define NTILES_L 782          // ceil(50000/64)
#define TSTRIDE  784

// ---------------- static scratch ----------------
__device__ float g_gi[BB * 768];
__device__ float g_gh[BB * 768];
__device__ float g_decctx[BB * 512];   // [h_new | context]
__device__ float g_hid[BB * EE];
__device__ float g_logits[(size_t)BB * VV];
__device__ float g_tmax[BB * TSTRIDE];
__device__ float g_tsum[BB * TSTRIDE];
__device__ float g_pgen[BB];

// ---------------- math helpers (MUFU only, no div.rn) ----------------
__device__ __forceinline__ float sigm(float x)   { return __fdividef(1.f, 1.f + __expf(-x)); }
__device__ __forceinline__ float tanh_e(float x) { return 1.f - __fdividef(2.f, __expf(2.f * x) + 1.f); }

// packed fp32x2 FMA (Blackwell-only PTX; exact fp32 semantics)
__device__ __forceinline__ void fma2(unsigned long long& d, unsigned long long a, unsigned long long b) {
    asm("fma.rn.f32x2 %0, %1, %2, %3;" : "=l"(d) : "l"(a), "l"(b), "l"(d));
}
__device__ __forceinline__ float unpack_sum(unsigned long long v) {
    float lo, hi;
    asm("mov.b64 {%0,%1}, %2;" : "=f"(lo), "=f"(hi) : "l"(v));
    return lo + hi;
}

// ---------------- init scratch ----------------
__global__ void init_kernel() {
    int i = blockIdx.x * 256 + threadIdx.x;   // grid 384 -> 98304
    if (i < BB * 768) { g_gi[i] = 0.f; g_gh[i] = 0.f; }
    if (i < BB * EE)  g_hid[i] = 0.f;
}

// ---------------- combined gi/gh split-K GEMM (one launch) ----------------
// blockIdx.y in [0,12): y<4 -> gi = emb[tok] @ w_ih^T (K=128, chunk y)
//                       y>=4 -> gh = hprev @ w_hh^T   (K=256, chunk y-4)
__global__ __launch_bounds__(256) void gates_gemm(
    const float* __restrict__ emb, const int* __restrict__ tok,
    const float* __restrict__ w_ih, const float* __restrict__ hprev,
    const float* __restrict__ w_hh)
{
    __shared__ float2 As[8][132];
    __shared__ float2 Ws[8][68];

    const int tid = threadIdx.x;
    const int tx = tid & 15;
    const int ty = tid >> 4;
    const int n0 = blockIdx.x * 64;
    const bool isGI = blockIdx.y < 4;
    const int  chunk = isGI ? blockIdx.y : (blockIdx.y - 4);
    const float* A = isGI ? emb : hprev;
    const float* W = isGI ? w_ih : w_hh;
    float* C = isGI ? g_gi : g_gh;
    const int K = isGI ? EE : HH;
    const int k0 = chunk * 32;
    const int kEnd = k0 + 32;

    unsigned long long acc[8][4];
#pragma unroll
    for (int i = 0; i < 8; i++)
#pragma unroll
        for (int j = 0; j < 4; j++) acc[i][j] = 0ULL;

    for (int kt = k0; kt < kEnd; kt += 16) {
        __syncthreads();
#pragma unroll
        for (int t = 0; t < 4; t++) {
            int lin = tid + t * 256;
            int m = lin >> 3, kp = lin & 7;
            int row = isGI ? tok[m] : m;
            As[kp][m] = *reinterpret_cast<const float2*>(A + (size_t)row * K + kt + 2 * kp);
        }
#pragma unroll
        for (int t = 0; t < 2; t++) {
            int lin = tid + t * 256;
            int nn = lin >> 3, kp = lin & 7;
            Ws[kp][nn] = *reinterpret_cast<const float2*>(W + (size_t)(n0 + nn) * K + kt + 2 * kp);
        }
        __syncthreads();

#pragma unroll
        for (int kp = 0; kp < 8; kp++) {
            unsigned long long a[8], w[4];
            const ulonglong2* ap = reinterpret_cast<const ulonglong2*>(&As[kp][ty * 8]);
            ulonglong2 q0 = ap[0], q1 = ap[1], q2 = ap[2], q3 = ap[3];
            a[0] = q0.x; a[1] = q0.y; a[2] = q1.x; a[3] = q1.y;
            a[4] = q2.x; a[5] = q2.y; a[6] = q3.x; a[7] = q3.y;
            const ulonglong2* wp = reinterpret_cast<const ulonglong2*>(&Ws[kp][tx * 4]);
            ulonglong2 r0 = wp[0], r1 = wp[1];
            w[0] = r0.x; w[1] = r0.y; w[2] = r1.x; w[3] = r1.y;
#pragma unroll
            for (int i = 0; i < 8; i++)
#pragma unroll
                for (int j = 0; j < 4; j++) fma2(acc[i][j], a[i], w[j]);
        }
    }

#pragma unroll
    for (int i = 0; i < 8; i++) {
        int m = ty * 8 + i;
#pragma unroll
        for (int j = 0; j < 4; j++) {
            int n = n0 + tx * 4 + j;
            atomicAdd(&C[(size_t)m * 768 + n], unpack_sum(acc[i][j]));
        }
    }
}

// ---------------- generic split-K GEMM for outh (N=128, K=512) ----------------
__global__ __launch_bounds__(256) void outh_gemm(
    const float* __restrict__ A, const float* __restrict__ W,
    const float* __restrict__ bias)
{
    __shared__ float2 As[8][132];
    __shared__ float2 Ws[8][68];

    const int tid = threadIdx.x;
    const int tx = tid & 15;
    const int ty = tid >> 4;
    const int n0 = blockIdx.x * 64;
    const int k0 = blockIdx.z * 32;
    const int kEnd = k0 + 32;

    unsigned long long acc[8][4];
#pragma unroll
    for (int i = 0; i < 8; i++)
#pragma unroll
        for (int j = 0; j < 4; j++) acc[i][j] = 0ULL;

    for (int kt = k0; kt < kEnd; kt += 16) {
        __syncthreads();
#pragma unroll
        for (int t = 0; t < 4; t++) {
            int lin = tid + t * 256;
            int m = lin >> 3, kp = lin & 7;
            As[kp][m] = *reinterpret_cast<const float2*>(A + (size_t)m * 512 + kt + 2 * kp);
        }
#pragma unroll
        for (int t = 0; t < 2; t++) {
            int lin = tid + t * 256;
            int nn = lin >> 3, kp = lin & 7;
            Ws[kp][nn] = *reinterpret_cast<const float2*>(W + (size_t)(n0 + nn) * 512 + kt + 2 * kp);
        }
        __syncthreads();

#pragma unroll
        for (int kp = 0; kp < 8; kp++) {
            unsigned long long a[8], w[4];
            const ulonglong2* ap = reinterpret_cast<const ulonglong2*>(&As[kp][ty * 8]);
            ulonglong2 q0 = ap[0], q1 = ap[1], q2 = ap[2], q3 = ap[3];
            a[0] = q0.x; a[1] = q0.y; a[2] = q1.x; a[3] = q1.y;
            a[4] = q2.x; a[5] = q2.y; a[6] = q3.x; a[7] = q3.y;
            const ulonglong2* wp = reinterpret_cast<const ulonglong2*>(&Ws[kp][tx * 4]);
            ulonglong2 r0 = wp[0], r1 = wp[1];
            w[0] = r0.x; w[1] = r0.y; w[2] = r1.x; w[3] = r1.y;
#pragma unroll
            for (int i = 0; i < 8; i++)
#pragma unroll
                for (int j = 0; j < 4; j++) fma2(acc[i][j], a[i], w[j]);
        }
    }

#pragma unroll
    for (int i = 0; i < 8; i++) {
        int m = ty * 8 + i;
#pragma unroll
        for (int j = 0; j < 4; j++) {
            int n = n0 + tx * 4 + j;
            float c = unpack_sum(acc[i][j]);
            if (blockIdx.z == 0 && bias) c += bias[n];
            atomicAdd(&g_hid[(size_t)m * EE + n], c);
        }
    }
}

// ---------------- mega-fused attention: GRU + scores + softmax + context + p_gen ----------------
// one block per batch row, 1024 threads
__global__ __launch_bounds__(1024) void attn_fused(
    const float* __restrict__ enc, const float* __restrict__ emb,
    const int* __restrict__ tok, const float* __restrict__ hprev,
    const float* __restrict__ b_ih, const float* __restrict__ b_hh,
    const float* __restrict__ w_s, const float* __restrict__ attb,
    const float* __restrict__ w_h, const float* __restrict__ attv,
    const float* __restrict__ genw, const float* __restrict__ genb,
    float* __restrict__ out_h, float* __restrict__ out_at,
    float* __restrict__ out_pg)
{
    const int b = blockIdx.x, t = threadIdx.x;
    __shared__ float wsh[HH], wh[HH], av[HH], hnews[HH], ctx[HH];
    __shared__ float att[SS];
    __shared__ float red[1024];

    // ---- stage 0: GRU for this row + smem param staging ----
    if (t < 256) {
        const float* gi = g_gi + b * 768;
        const float* gh = g_gh + b * 768;
        float ir = gi[t]       + __ldg(b_ih + t);
        float iz = gi[256 + t] + __ldg(b_ih + 256 + t);
        float in_ = gi[512 + t] + __ldg(b_ih + 512 + t);
        float hr = gh[t]       + __ldg(b_hh + t);
        float hz = gh[256 + t] + __ldg(b_hh + 256 + t);
        float hn = gh[512 + t] + __ldg(b_hh + 512 + t);
        float r = sigm(ir + hr);
        float z = sigm(iz + hz);
        float n = tanh_e(in_ + r * hn);
        float hp = hprev[b * HH + t];
        float hnew = (1.f - z) * n + z * hp;
        hnews[t] = hnew;
        out_h[b * HH + t] = hnew;
        g_decctx[b * 512 + t] = hnew;
        wsh[t] = fmaf(__ldg(w_s + t), hnew, __ldg(attb));
    } else if (t < 512) {
        wh[t - 256] = __ldg(w_h + (t - 256));
    } else if (t < 768) {
        av[t - 512] = __ldg(attv + (t - 512));
    }
    __syncthreads();

    // ---- stage 1: scores (32 warps over 400 rows) ----
    {
        const int wid = t >> 5, lane = t & 31;
        const int h0 = lane * 8;
        float4 w0 = *reinterpret_cast<const float4*>(wh  + h0);
        float4 w1 = *reinterpret_cast<const float4*>(wh  + h0 + 4);
        float4 s0 = *reinterpret_cast<const float4*>(wsh + h0);
        float4 s1 = *reinterpret_cast<const float4*>(wsh + h0 + 4);
        float4 v0 = *reinterpret_cast<const float4*>(av  + h0);
        float4 v1 = *reinterpret_cast<const float4*>(av  + h0 + 4);
        for (int s = wid; s < SS; s += 32) {
            const float4* e = reinterpret_cast<const float4*>(enc + ((size_t)b * SS + s) * HH + h0);
            float4 e0 = e[0], e1 = e[1];
            float sum;
            sum  = v0.x * tanh_e(fmaf(w0.x, e0.x, s0.x));
            sum += v0.y * tanh_e(fmaf(w0.y, e0.y, s0.y));
            sum += v0.z * tanh_e(fmaf(w0.z, e0.z, s0.z));
            sum += v0.w * tanh_e(fmaf(w0.w, e0.w, s0.w));
            sum += v1.x * tanh_e(fmaf(w1.x, e1.x, s1.x));
            sum += v1.y * tanh_e(fmaf(w1.y, e1.y, s1.y));
            sum += v1.z * tanh_e(fmaf(w1.z, e1.z, s1.z));
            sum += v1.w * tanh_e(fmaf(w1.w, e1.w, s1.w));
#pragma unroll
            for (int o = 16; o; o >>= 1) sum += __shfl_xor_sync(0xffffffffu, sum, o);
            if (lane == 0) att[s] = sum;
        }
    }
    __syncthreads();

    // ---- stage 2: softmax over S=400 ----
    float v = (t < SS) ? att[t] : -INFINITY;
    red[t] = v; __syncthreads();
#pragma unroll
    for (int o = 512; o; o >>= 1) { if (t < o) red[t] = fmaxf(red[t], red[t + o]); __syncthreads(); }
    float mx = red[0]; __syncthreads();
    float ev = (t < SS) ? __expf(v - mx) : 0.f;
    red[t] = ev; __syncthreads();
#pragma unroll
    for (int o = 512; o; o >>= 1) { if (t < o) red[t] += red[t + o]; __syncthreads(); }
    float inv = __fdividef(1.f, red[0]); __syncthreads();
    if (t < SS) {
        float a = ev * inv;
        att[t] = a;
        out_at[b * SS + t] = a;
    }
    __syncthreads();

    // ---- stage 3: context (4-way S split per h) ----
    {
        int h = t & 255;
        int part = t >> 8;
        int sBeg = part * 100;
        const float* e = enc + (size_t)b * SS * HH + (size_t)sBeg * HH + h;
        float c = 0.f;
#pragma unroll 10
        for (int s = 0; s < 100; s++) c = fmaf(att[sBeg + s], e[(size_t)s * HH], c);
        red[t] = c;
    }
    __syncthreads();
    if (t < 512) red[t] += red[t + 512];
    __syncthreads();
    if (t < 256) {
        float c = red[t] + red[t + 256];
        ctx[t] = c;
        g_decctx[b * 512 + 256 + t] = c;
    }
    __syncthreads();

    // ---- stage 4: p_gen ----
    float pv = 0.f;
    if (t < 256)      pv = hnews[t] * __ldg(genw + t);
    else if (t < 512) pv = ctx[t - 256] * __ldg(genw + t);
    else if (t < 640) pv = emb[(size_t)tok[b] * EE + (t - 512)] * __ldg(genw + t);
    red[t] = pv; __syncthreads();
#pragma unroll
    for (int o = 512; o; o >>= 1) { if (t < o) red[t] += red[t + o]; __syncthreads(); }
    if (t == 0) {
        float p = sigm(red[0] + __ldg(genb));
        out_pg[b] = p;
        g_pgen[b] = p;
    }
}

// ---------------- logits GEMM (FFMA2) + fused bias / tile-max / tile-sumexp ----------------
__global__ __launch_bounds__(256, 2) void logits_kernel(
    const float* __restrict__ A, const float* __restrict__ W,
    const float* __restrict__ bias, float* __restrict__ C)
{
    __shared__ float2 As[8][132];
    __shared__ float2 Ws[8][68];

    const int tid = threadIdx.x;
    const int tx = tid & 15;
    const int ty = tid >> 4;
    const int n0 = blockIdx.x * 64;

    unsigned long long acc[8][4];
#pragma unroll
    for (int i = 0; i < 8; i++)
#pragma unroll
        for (int j = 0; j < 4; j++) acc[i][j] = 0ULL;

    for (int kt = 0; kt < EE; kt += 16) {
        __syncthreads();
#pragma unroll
        for (int t = 0; t < 4; t++) {
            int lin = tid + t * 256;
            int m = lin >> 3, kp = lin & 7;
            As[kp][m] = *reinterpret_cast<const float2*>(A + (size_t)m * EE + kt + 2 * kp);
        }
#pragma unroll
        for (int t = 0; t < 2; t++) {
            int lin = tid + t * 256;
            int nn = lin >> 3, kp = lin & 7;
            int row = n0 + nn;
            if (row >= VV) row = VV - 1;
            Ws[kp][nn] = *reinterpret_cast<const float2*>(W + (size_t)row * EE + kt + 2 * kp);
        }
        __syncthreads();

#pragma unroll
        for (int kp = 0; kp < 8; kp++) {
            unsigned long long a[8], w[4];
            const ulonglong2* ap = reinterpret_cast<const ulonglong2*>(&As[kp][ty * 8]);
            ulonglong2 q0 = ap[0], q1 = ap[1], q2 = ap[2], q3 = ap[3];
            a[0] = q0.x; a[1] = q0.y; a[2] = q1.x; a[3] = q1.y;
            a[4] = q2.x; a[5] = q2.y; a[6] = q3.x; a[7] = q3.y;
            const ulonglong2* wp = reinterpret_cast<const ulonglong2*>(&Ws[kp][tx * 4]);
            ulonglong2 r0 = wp[0], r1 = wp[1];
            w[0] = r0.x; w[1] = r0.y; w[2] = r1.x; w[3] = r1.y;
#pragma unroll
            for (int i = 0; i < 8; i++)
#pragma unroll
                for (int j = 0; j < 4; j++) fma2(acc[i][j], a[i], w[j]);
        }
    }

#pragma unroll
    for (int i = 0; i < 8; i++) {
        int m = ty * 8 + i;
        float vls[4];
        float mloc = -INFINITY;
#pragma unroll
        for (int j = 0; j < 4; j++) {
            int n = n0 + tx * 4 + j;
            bool valid = n < VV;
            int nc = valid ? n : VV - 1;
            float c = unpack_sum(acc[i][j]) + __ldg(bias + nc);
            if (valid) {
                C[(size_t)m * VV + n] = c;
                mloc = fmaxf(mloc, c);
                vls[j] = c;
            } else {
                vls[j] = -INFINITY;
            }
        }
#pragma unroll
        for (int o = 8; o; o >>= 1) mloc = fmaxf(mloc, __shfl_xor_sync(0xffffffffu, mloc, o));
        float s = 0.f;
#pragma unroll
        for (int j = 0; j < 4; j++) if (vls[j] > -INFINITY) s += __expf(vls[j] - mloc);
#pragma unroll
        for (int o = 8; o; o >>= 1) s += __shfl_xor_sync(0xffffffffu, s, o);
        if (tx == 0) {
            g_tmax[m * TSTRIDE + blockIdx.x] = mloc;
            g_tsum[m * TSTRIDE + blockIdx.x] = s;
        }
    }
}

// ---------------- finalize (fused merge) ----------------
__global__ __launch_bounds__(256) void finalize_kernel(float* __restrict__ out_pv, float* __restrict__ out_pf)
{
    int b = blockIdx.y, t = threadIdx.x;
    __shared__ float red[256];

    // in-block merge of 782 tile partials
    float mx = -INFINITY;
    for (int i = t; i < NTILES_L; i += 256) mx = fmaxf(mx, g_tmax[b * TSTRIDE + i]);
    red[t] = mx; __syncthreads();
#pragma unroll
    for (int o = 128; o; o >>= 1) { if (t < o) red[t] = fmaxf(red[t], red[t + o]); __syncthreads(); }
    mx = red[0]; __syncthreads();
    float s = 0.f;
    for (int i = t; i < NTILES_L; i += 256)
        s += g_tsum[b * TSTRIDE + i] * __expf(g_tmax[b * TSTRIDE + i] - mx);
    red[t] = s; __syncthreads();
#pragma unroll
    for (int o = 128; o; o >>= 1) { if (t < o) red[t] += red[t + o]; __syncthreads(); }
    float inv = __fdividef(1.f, red[0]);
    float pg = g_pgen[b];

    int start = blockIdx.x * 2000;
    const float* lg = g_logits + (size_t)b * VV + start;
    float* pv = out_pv + (size_t)b * VV + start;
    float* pf = out_pf + (size_t)b * VP + start;
    for (int i = t; i < 2000; i += 256) {
        float e = __expf(lg[i] - mx) * inv;
        pv[i] = e;
        pf[i] = e * pg;
    }
    if (blockIdx.x == 0 && t < PADV) out_pf[(size_t)b * VP + VV + t] = 0.f;
}

// ---------------- copy-mechanism scatter ----------------
__global__ void scatter_kernel(const int* __restrict__ fiv, const float* __restrict__ att,
                               float* __restrict__ out_pf)
{
    int b = blockIdx.x, s = threadIdx.x;
    if (s < SS) {
        float w = (1.f - g_pgen[b]) * att[b * SS + s];
        atomicAdd(&out_pf[(size_t)b * VP + fiv[b * SS + s]], w);
    }
}

// ---------------- launch ----------------
extern "C" void kernel_launch(void* const* d_in, const int* in_sizes, int n_in,
                              void* d_out, int out_size)
{
    const int*   tok   = (const int*)d_in[0];
    const float* hprev = (const float*)d_in[1];
    const float* enc   = (const float*)d_in[2];
    const int*   fiv   = (const int*)d_in[3];
    const float* emb   = (const float*)d_in[4];
    const float* w_ih  = (const float*)d_in[5];
    const float* w_hh  = (const float*)d_in[6];
    const float* b_ih  = (const float*)d_in[7];
    const float* b_hh  = (const float*)d_in[8];
    const float* w_h   = (const float*)d_in[9];
    const float* w_s   = (const float*)d_in[10];
    const float* attb  = (const float*)d_in[11];
    const float* attv  = (const float*)d_in[12];
    const float* genw  = (const float*)d_in[13];
    const float* genb  = (const float*)d_in[14];
    const float* outhw = (const float*)d_in[15];
    const float* outhb = (const float*)d_in[16];
    const float* outvw = (const float*)d_in[17];
    const float* outvb = (const float*)d_in[18];

    float* out    = (float*)d_out;
    float* out_h  = out;
    float* out_pf = out + 32768;
    float* out_pg = out + 6464768;
    float* out_pv = out + 6464896;
    float* out_at = out + 12864896;

    float *p_hid, *p_logits, *p_dc;
    cudaGetSymbolAddress((void**)&p_hid,    g_hid);
    cudaGetSymbolAddress((void**)&p_logits, g_logits);
    cudaGetSymbolAddress((void**)&p_dc,     g_decctx);

    init_kernel<<<384, 256>>>();

    gates_gemm<<<dim3(12, 12), 256>>>(emb, tok, w_ih, hprev, w_hh);

    attn_fused<<<128, 1024>>>(enc, emb, tok, hprev, b_ih, b_hh, w_s, attb,
                              w_h, attv, genw, genb, out_h, out_at, out_pg);

    outh_gemm<<<dim3(2, 1, 16), 256>>>(p_dc, outhw, outhb);

    logits_kernel<<<NTILES_L, 256>>>(p_hid, outvw, outvb, p_logits);

    finalize_kernel<<<dim3(25, 128), 256>>>(out_pv, out_pf);
    scatter_kernel<<<128, 512>>>(fiv, out_at, out_pf);
}